// round 8
// baseline (speedup 1.0000x reference)
#include <cuda_runtime.h>
#include <cuda_bf16.h>
#include <cstdint>

// input_spikes: [B=32, C=3, H=128, W=128, T=50] f32; weight/gain/bias: [C,H,W]
// Output = spikes [B,C,H,W,T] ++ final_v [B,C,H,W] ++ final_reset [B,C,H,W]

#define T_STEPS      50
#define PIX_PER_BLK  128
#define REGION_FLOATS (PIX_PER_BLK * T_STEPS)   // 6400
#define REGION_BYTES  (REGION_FLOATS * 4)       // 25600
#define CHUNK_PIX    32                         // one warp's pixels
#define CHUNK_BYTES  (CHUNK_PIX * T_STEPS * 4)  // 6400
#define NWARPS       4
#define CHW          49152                      // 3*128*128
#define TOTAL_PIX    1572864                    // 32*49152
#define SPIKES_ELEMS 78643200LL
#define NUM_REGIONS  12288
#define PREFETCH_DIST 512                       // validated in R6: single-read + early L2

__device__ __forceinline__ float lif_decay() { return 0.77880078307140486825f; }

__device__ __forceinline__ void mbar_wait0(uint32_t mbar) {
    uint32_t done;
    asm volatile(
        "{\n\t.reg .pred p;\n\t"
        "mbarrier.try_wait.parity.acquire.cta.shared::cta.b64 p, [%1], 0;\n\t"
        "selp.b32 %0, 1, 0, p;\n\t}"
        : "=r"(done) : "r"(mbar) : "memory");
    if (!done) {
        asm volatile(
            "{\n\t.reg .pred P1;\n\t"
            "WAIT_LOOP_%=:\n\t"
            "mbarrier.try_wait.parity.acquire.cta.shared::cta.b64 P1, [%0], 0, 0x989680;\n\t"
            "@P1 bra.uni WAIT_DONE_%=;\n\t"
            "bra.uni WAIT_LOOP_%=;\n\t"
            "WAIT_DONE_%=:\n\t}"
            :: "r"(mbar) : "memory");
    }
}

__global__ void __launch_bounds__(PIX_PER_BLK)
lif_kernel(const float* __restrict__ x,
           const float* __restrict__ w,
           const float* __restrict__ g,
           float* __restrict__ out_spikes,
           float* __restrict__ out_final_v,
           float* __restrict__ out_final_r)
{
    __shared__ __align__(128) float s[REGION_FLOATS];   // 25,600 B
    __shared__ __align__(8)   uint64_t mbar[NWARPS];

    const int tid  = threadIdx.x;
    const int wid  = tid >> 5;
    const int lane = tid & 31;
    const long long base_pix = (long long)blockIdx.x * PIX_PER_BLK;

    const uint32_t smem_s  = (uint32_t)__cvta_generic_to_shared(s);
    const uint32_t my_mbar = (uint32_t)__cvta_generic_to_shared(&mbar[wid]);
    const uint32_t my_chunk = smem_s + (uint32_t)(wid * CHUNK_BYTES);

    // ---- per-warp: init own barrier, issue own 6.4KB bulk load. No CTA syncs. ----
    if (lane == 0) {
        asm volatile("mbarrier.init.shared.b64 [%0], %1;"
                     :: "r"(my_mbar), "r"(1) : "memory");
        asm volatile("fence.proxy.async.shared::cta;" ::: "memory");
        asm volatile("mbarrier.arrive.expect_tx.shared.b64 _, [%0], %1;"
                     :: "r"(my_mbar), "r"(CHUNK_BYTES) : "memory");
        const float* src = x + base_pix * T_STEPS + wid * (CHUNK_PIX * T_STEPS);
        asm volatile(
            "cp.async.bulk.shared::cta.global.mbarrier::complete_tx::bytes "
            "[%0], [%1], %2, [%3];"
            :: "r"(my_chunk), "l"(src), "r"(CHUNK_BYTES), "r"(my_mbar)
            : "memory");

        // L2 prefetch (~half a wave ahead), one per CTA.
        if (wid == 0) {
            const long long pf_region = (long long)blockIdx.x + PREFETCH_DIST;
            if (pf_region < NUM_REGIONS) {
                const float* pf = x + pf_region * (long long)REGION_FLOATS;
                asm volatile("cp.async.bulk.prefetch.L2.global [%0], %1;"
                             :: "l"(pf), "r"(CHUNK_BYTES * NWARPS) : "memory");
            }
        }
    }
    __syncwarp();
    mbar_wait0(my_mbar);   // wait only for this warp's 6.4KB

    // ---- per-pixel LIF recurrence over T, spikes written back in place ----
    const long long gp  = base_pix + tid;
    const int       chw = (int)(gp % CHW);

    const float decay = lif_decay();
    const float omd   = 1.0f - decay;
    const float wv = w[chw];
    const float gv = g[chw];

    // Thread's row: byte offset tid*200 (inside this warp's chunk), 8B aligned.
    float2* srow = reinterpret_cast<float2*>(s + tid * T_STEPS);

    float v = 0.0f, r = 0.0f;
    #pragma unroll
    for (int i = 0; i < T_STEPS / 2; ++i) {
        float2 xx = srow[i];

        float wp0 = wv * xx.x;
        v = v * decay + gv * wp0 * omd;          // reference op order
        float sp0 = (v > 1.0f) ? 1.0f : 0.0f;
        r = r * decay + sp0;

        float wp1 = wv * xx.y;
        v = v * decay + gv * wp1 * omd;
        float sp1 = (v > 1.0f) ? 1.0f : 0.0f;
        r = r * decay + sp1;

        srow[i] = make_float2(sp0, sp1);
    }
    out_final_v[gp] = v;
    out_final_r[gp] = r;

    __syncwarp();          // this warp's 32 pixel-rows complete in smem

    // ---- per-warp bulk store of its own 6.4KB chunk ----
    if (lane == 0) {
        asm volatile("fence.proxy.async.shared::cta;" ::: "memory");
        float* dst = out_spikes + base_pix * T_STEPS + wid * (CHUNK_PIX * T_STEPS);
        asm volatile(
            "cp.async.bulk.global.shared::cta.bulk_group [%0], [%1], %2;"
            :: "l"(dst), "r"(my_chunk), "r"(CHUNK_BYTES) : "memory");
        asm volatile("cp.async.bulk.commit_group;" ::: "memory");
        asm volatile("cp.async.bulk.wait_group 0;" ::: "memory");
    }
}

extern "C" void kernel_launch(void* const* d_in, const int* in_sizes, int n_in,
                              void* d_out, int out_size)
{
    const float* x = (const float*)d_in[0];   // input_spikes
    const float* w = (const float*)d_in[1];   // weight
    const float* g = (const float*)d_in[2];   // gain
    // d_in[3] = bias: unused by the reference computation

    float* out        = (float*)d_out;
    float* out_spikes = out;
    float* out_vf     = out + SPIKES_ELEMS;
    float* out_rf     = out + SPIKES_ELEMS + TOTAL_PIX;

    const int blocks = TOTAL_PIX / PIX_PER_BLK;  // 12288
    lif_kernel<<<blocks, PIX_PER_BLK>>>(x, w, g, out_spikes, out_vf, out_rf);
}

// round 10
// speedup vs baseline: 1.0265x; 1.0265x over previous
#include <cuda_runtime.h>
#include <cuda_bf16.h>
#include <cstdint>

// input_spikes: [B=32, C=3, H=128, W=128, T=50] f32; weight/gain/bias: [C,H,W]
// Output = spikes [B,C,H,W,T] ++ final_v [B,C,H,W] ++ final_reset [B,C,H,W]

#define T_STEPS      50
#define PIX_PER_BLK  128
#define REGION_FLOATS (PIX_PER_BLK * T_STEPS)   // 6400
#define REGION_BYTES  (REGION_FLOATS * 4)       // 25600
#define CHW          49152                      // 3*128*128
#define TOTAL_PIX    1572864                    // 32*49152
#define SPIKES_ELEMS 78643200LL
#define NUM_REGIONS  12288
// Validated in R6: single-read traffic with early-L2 conversion of cold waits.
#define PREFETCH_DIST 512

__device__ __forceinline__ float lif_decay() { return 0.77880078307140486825f; }

__global__ void __launch_bounds__(PIX_PER_BLK)
lif_kernel(const float* __restrict__ x,
           const float* __restrict__ w,
           const float* __restrict__ g,
           float* __restrict__ out_spikes,
           float* __restrict__ out_final_v,
           float* __restrict__ out_final_r)
{
    __shared__ __align__(128) float s[REGION_FLOATS];   // 25,600 B
    __shared__ __align__(8)   uint64_t mbar;

    const int tid = threadIdx.x;
    const long long base_pix = (long long)blockIdx.x * PIX_PER_BLK;

    const uint32_t smem_s    = (uint32_t)__cvta_generic_to_shared(s);
    const uint32_t smem_mbar = (uint32_t)__cvta_generic_to_shared(&mbar);

    // ---- mbarrier init + TMA bulk load of this CTA's contiguous region ----
    if (tid == 0) {
        // Dead-on-arrival lines (consumed input, written output) are marked
        // evict_first so L2 capacity stays dedicated to the prefetch window.
        uint64_t pol_ef;
        asm volatile("createpolicy.fractional.L2::evict_first.b64 %0, 1.0;"
                     : "=l"(pol_ef));

        asm volatile("mbarrier.init.shared.b64 [%0], %1;"
                     :: "r"(smem_mbar), "r"(1) : "memory");
        asm volatile("fence.proxy.async.shared::cta;" ::: "memory");
        asm volatile("mbarrier.arrive.expect_tx.shared.b64 _, [%0], %1;"
                     :: "r"(smem_mbar), "r"(REGION_BYTES) : "memory");
        const float* src = x + base_pix * T_STEPS;
        // After this load consumes them into smem, the input lines are dead:
        // evict_first.
        asm volatile(
            "cp.async.bulk.shared::cta.global.mbarrier::complete_tx::bytes"
            ".L2::cache_hint [%0], [%1], %2, [%3], %4;"
            :: "r"(smem_s), "l"(src), "r"(REGION_BYTES), "r"(smem_mbar),
               "l"(pol_ef)
            : "memory");

        // L2 prefetch ~half a wave ahead (default policy: must stay resident).
        const long long pf_region = (long long)blockIdx.x + PREFETCH_DIST;
        if (pf_region < NUM_REGIONS) {
            const float* pf = x + pf_region * (long long)REGION_FLOATS;
            asm volatile("cp.async.bulk.prefetch.L2.global [%0], %1;"
                         :: "l"(pf), "r"(REGION_BYTES) : "memory");
        }
    }
    __syncthreads();

    // ---- wait for bulk-load completion (phase parity 0) ----
    {
        uint32_t done;
        asm volatile(
            "{\n\t.reg .pred p;\n\t"
            "mbarrier.try_wait.parity.acquire.cta.shared::cta.b64 p, [%1], 0;\n\t"
            "selp.b32 %0, 1, 0, p;\n\t}"
            : "=r"(done) : "r"(smem_mbar) : "memory");
        if (!done) {
            asm volatile(
                "{\n\t.reg .pred P1;\n\t"
                "WAIT_LOOP_%=:\n\t"
                "mbarrier.try_wait.parity.acquire.cta.shared::cta.b64 P1, [%0], 0, 0x989680;\n\t"
                "@P1 bra.uni WAIT_DONE_%=;\n\t"
                "bra.uni WAIT_LOOP_%=;\n\t"
                "WAIT_DONE_%=:\n\t}"
                :: "r"(smem_mbar) : "memory");
        }
    }

    // ---- per-pixel LIF recurrence over T, spikes written back in place ----
    const long long gp  = base_pix + tid;
    const int       chw = (int)(gp % CHW);

    const float decay = lif_decay();
    const float omd   = 1.0f - decay;
    const float wv = w[chw];
    const float gv = g[chw];

    // Thread's row: byte offset tid*200 -> 8B aligned, so float2 is legal.
    float2* srow = reinterpret_cast<float2*>(s + tid * T_STEPS);

    float v = 0.0f, r = 0.0f;
    #pragma unroll
    for (int i = 0; i < T_STEPS / 2; ++i) {
        float2 xx = srow[i];

        float wp0 = wv * xx.x;
        v = v * decay + gv * wp0 * omd;          // reference op order
        float sp0 = (v > 1.0f) ? 1.0f : 0.0f;
        r = r * decay + sp0;

        float wp1 = wv * xx.y;
        v = v * decay + gv * wp1 * omd;
        float sp1 = (v > 1.0f) ? 1.0f : 0.0f;
        r = r * decay + sp1;

        srow[i] = make_float2(sp0, sp1);
    }
    out_final_v[gp] = v;
    out_final_r[gp] = r;

    __syncthreads();

    // ---- TMA bulk store of spikes (write-once lines: evict_first) ----
    if (tid == 0) {
        uint64_t pol_ef;
        asm volatile("createpolicy.fractional.L2::evict_first.b64 %0, 1.0;"
                     : "=l"(pol_ef));
        asm volatile("fence.proxy.async.shared::cta;" ::: "memory");
        float* dst = out_spikes + base_pix * T_STEPS;
        asm volatile(
            "cp.async.bulk.global.shared::cta.bulk_group.L2::cache_hint "
            "[%0], [%1], %2, %3;"
            :: "l"(dst), "r"(smem_s), "r"(REGION_BYTES), "l"(pol_ef)
            : "memory");
        asm volatile("cp.async.bulk.commit_group;" ::: "memory");
        asm volatile("cp.async.bulk.wait_group 0;" ::: "memory");
    }
}

extern "C" void kernel_launch(void* const* d_in, const int* in_sizes, int n_in,
                              void* d_out, int out_size)
{
    const float* x = (const float*)d_in[0];   // input_spikes
    const float* w = (const float*)d_in[1];   // weight
    const float* g = (const float*)d_in[2];   // gain
    // d_in[3] = bias: unused by the reference computation

    float* out        = (float*)d_out;
    float* out_spikes = out;
    float* out_vf     = out + SPIKES_ELEMS;
    float* out_rf     = out + SPIKES_ELEMS + TOTAL_PIX;

    const int blocks = TOTAL_PIX / PIX_PER_BLK;  // 12288
    lif_kernel<<<blocks, PIX_PER_BLK>>>(x, w, g, out_spikes, out_vf, out_rf);
}